// round 9
// baseline (speedup 1.0000x reference)
#include <cuda_runtime.h>
#include <cstdint>

// Problem dims (fixed by the reference)
#define EDIM 1024
#define RDIM 16
#define BATCH 4
#define SLEN 2048
#define MTOT (BATCH * SLEN)   // 8192

// ---------------- device scratch (no allocations allowed) ----------------
__device__ float g_weff[3][EDIM * EDIM];                 // Q,K,V effective weights (tf32)
__device__ float g_xq[(size_t)MTOT * EDIM];              // tf32 copies of inputs
__device__ float g_xk[(size_t)MTOT * EDIM];
__device__ float g_xv[(size_t)MTOT * EDIM];
__device__ float g_ow[EDIM * EDIM];
__device__ float g_q[(size_t)MTOT * EDIM];
__device__ float g_k[(size_t)MTOT * EDIM];
__device__ float g_vT[(size_t)EDIM * MTOT];              // V projection, transposed
__device__ float g_scores[(size_t)BATCH * SLEN * SLEN];
__device__ float g_ctx[(size_t)MTOT * EDIM];

__device__ __forceinline__ float rtf(float f) {          // round-to-nearest tf32, as fp32 bits
    uint32_t u;
    asm("cvt.rna.tf32.f32 %0, %1;" : "=r"(u) : "f"(f));
    return __uint_as_float(u);
}

// ---- elementwise tf32 rounding copy (float4 granularity) ----
__global__ void round_tf32_kernel(const float4* __restrict__ src, float4* __restrict__ dst) {
    size_t i = (size_t)blockIdx.x * blockDim.x + threadIdx.x;
    float4 v = src[i];
    v.x = rtf(v.x); v.y = rtf(v.y); v.z = rtf(v.z); v.w = rtf(v.w);
    dst[i] = v;
}

// ---- fold LoRA: Weff[f][e] = tf32(W[f][e] + sum_r B[f][r]*A[r][e]) ----
__global__ void fold_lora_kernel(const float* __restrict__ W0, const float* __restrict__ B0,
                                 const float* __restrict__ A0,
                                 const float* __restrict__ W1, const float* __restrict__ B1,
                                 const float* __restrict__ A1,
                                 const float* __restrict__ W2, const float* __restrict__ B2,
                                 const float* __restrict__ A2,
                                 float* __restrict__ Weff) {
    const float *W, *Bm, *Am;
    if (blockIdx.z == 0)      { W = W0; Bm = B0; Am = A0; }
    else if (blockIdx.z == 1) { W = W1; Bm = B1; Am = A1; }
    else                      { W = W2; Bm = B2; Am = A2; }
    float* dst = Weff + (size_t)blockIdx.z * EDIM * EDIM;
    int idx = blockIdx.x * blockDim.x + threadIdx.x;
    int f = idx >> 10;
    int e = idx & (EDIM - 1);
    float acc = W[idx];
#pragma unroll
    for (int r = 0; r < RDIM; r++) acc += Bm[f * RDIM + r] * Am[r * EDIM + e];
    dst[idx] = rtf(acc);
}

// ======== tf32 mma.sync NT GEMM: C[m][n] = alpha * sum_k A[m][k]*B[n][k] ========
// Inputs MUST already be tf32-rounded in memory. Fragments loaded via ldmatrix
// (32-bit tf32 elements ride as b16 pairs; tile mapping == mma fragment layout).
// Block tile 128x128x32, 8 warps (2 x 4), warp tile 64x32, mma m16n8k8.
#define BM 128
#define BN 128
#define BK 32
#define SMSTRIDE 36                         // floats per row (32 + 4 pad)
#define TILE_F (128 * SMSTRIDE)
#define STAGE_F (2 * TILE_F)
#define GEMM_SMEM (2 * STAGE_F * 4)         // 2 stages, 73728 bytes

__device__ __forceinline__ void mma_tf32(float c[4], const uint32_t a[4], const uint32_t b[2]) {
    asm volatile(
        "mma.sync.aligned.m16n8k8.row.col.f32.tf32.tf32.f32 "
        "{%0,%1,%2,%3}, {%4,%5,%6,%7}, {%8,%9}, {%0,%1,%2,%3};"
        : "+f"(c[0]), "+f"(c[1]), "+f"(c[2]), "+f"(c[3])
        : "r"(a[0]), "r"(a[1]), "r"(a[2]), "r"(a[3]), "r"(b[0]), "r"(b[1]));
}

__device__ __forceinline__ void ldsm_x4(uint32_t r[4], uint32_t addr) {
    asm volatile("ldmatrix.sync.aligned.m8n8.x4.shared.b16 {%0,%1,%2,%3}, [%4];"
                 : "=r"(r[0]), "=r"(r[1]), "=r"(r[2]), "=r"(r[3]) : "r"(addr));
}
__device__ __forceinline__ void ldsm_x2(uint32_t r[2], uint32_t addr) {
    asm volatile("ldmatrix.sync.aligned.m8n8.x2.shared.b16 {%0,%1}, [%2];"
                 : "=r"(r[0]), "=r"(r[1]) : "r"(addr));
}

__global__ __launch_bounds__(256) void gemm_tc_kernel(
    const float* __restrict__ A, const float* __restrict__ B, float* __restrict__ C,
    int ldA, int ldB, int ldC, int Kdim, float alpha, int transC, int roundC,
    long sA, long sB, long sC) {
    extern __shared__ __align__(16) float sm[];
    uint32_t smb;
    asm("{ .reg .u64 u; cvta.to.shared.u64 u, %1; cvt.u32.u64 %0, u; }" : "=r"(smb) : "l"(sm));
    A += (size_t)blockIdx.z * sA + (size_t)blockIdx.y * BM * ldA;
    B += (size_t)blockIdx.z * sB + (size_t)blockIdx.x * BN * ldB;
    C += (size_t)blockIdx.z * sC;
    const int tid = threadIdx.x;
    const int wid = tid >> 5, lid = tid & 31;
    const int wm = wid & 1, wn = wid >> 1;      // warp grid 2 x 4
    const int mb = wm * 64, nb = wn * 32;
    const int g = lid >> 2, t = lid & 3;

    // ldmatrix lane->address offsets (bytes, relative to stage A / B base)
    uint32_t a_off[4], b_off[4];
#pragma unroll
    for (int im = 0; im < 4; im++)
        a_off[im] = ((mb + im * 16 + (lid & 15)) * SMSTRIDE + (lid >> 4) * 4) * 4;
#pragma unroll
    for (int in = 0; in < 4; in++)
        b_off[in] = ((nb + in * 8 + (lid & 7)) * SMSTRIDE + ((lid >> 3) & 1) * 4) * 4
                    + TILE_F * 4;

    float acc[4][4][4];
#pragma unroll
    for (int im = 0; im < 4; im++)
#pragma unroll
        for (int in = 0; in < 4; in++)
#pragma unroll
            for (int q = 0; q < 4; q++) acc[im][in][q] = 0.f;

    const int NT = Kdim / BK;

#define LOAD_TILE(KT, S)                                                          \
    do {                                                                          \
        float* as = sm + (S) * STAGE_F;                                           \
        float* bs = as + TILE_F;                                                  \
        const float* Ag = A + (size_t)(KT) * BK;                                  \
        const float* Bg = B + (size_t)(KT) * BK;                                  \
        _Pragma("unroll")                                                         \
        for (int j = 0; j < 4; j++) {                                             \
            int idx = j * 256 + tid;                                              \
            int r = idx >> 3, q = idx & 7;                                        \
            uint32_t so;                                                          \
            asm("{ .reg .u64 u; cvta.to.shared.u64 u, %1; cvt.u32.u64 %0, u; }"   \
                : "=r"(so) : "l"(as + r * SMSTRIDE + q * 4));                     \
            asm volatile("cp.async.cg.shared.global [%0], [%1], 16;"              \
                         :: "r"(so), "l"(Ag + (size_t)r * ldA + q * 4));          \
        }                                                                         \
        _Pragma("unroll")                                                         \
        for (int j = 0; j < 4; j++) {                                             \
            int idx = j * 256 + tid;                                              \
            int r = idx >> 3, q = idx & 7;                                        \
            uint32_t so;                                                          \
            asm("{ .reg .u64 u; cvta.to.shared.u64 u, %1; cvt.u32.u64 %0, u; }"   \
                : "=r"(so) : "l"(bs + r * SMSTRIDE + q * 4));                     \
            asm volatile("cp.async.cg.shared.global [%0], [%1], 16;"              \
                         :: "r"(so), "l"(Bg + (size_t)r * ldB + q * 4));          \
        }                                                                         \
        asm volatile("cp.async.commit_group;" ::: "memory");                      \
    } while (0)

    LOAD_TILE(0, 0);
    if (NT > 1) LOAD_TILE(1, 1);

    for (int kt = 0; kt < NT; kt++) {
        if (kt + 1 < NT)
            asm volatile("cp.async.wait_group 1;" ::: "memory");
        else
            asm volatile("cp.async.wait_group 0;" ::: "memory");
        __syncthreads();

        const uint32_t stg = smb + (kt & 1) * (STAGE_F * 4);

        uint32_t ua[2][4][4], ub[2][4][2];
        // prefetch ks=0 fragments
#pragma unroll
        for (int im = 0; im < 4; im++) ldsm_x4(ua[0][im], stg + a_off[im]);
#pragma unroll
        for (int in = 0; in < 4; in++) ldsm_x2(ub[0][in], stg + b_off[in]);

#pragma unroll
        for (int ks = 0; ks < 4; ks++) {
            const int cur = ks & 1, nxt = cur ^ 1;
            if (ks < 3) {
                const uint32_t ko = (ks + 1) * 32;   // 8 floats = 32 bytes
#pragma unroll
                for (int im = 0; im < 4; im++) ldsm_x4(ua[nxt][im], stg + a_off[im] + ko);
#pragma unroll
                for (int in = 0; in < 4; in++) ldsm_x2(ub[nxt][in], stg + b_off[in] + ko);
            }
#pragma unroll
            for (int im = 0; im < 4; im++)
#pragma unroll
                for (int in = 0; in < 4; in++) mma_tf32(acc[im][in], ua[cur][im], ub[cur][in]);
        }
        __syncthreads();
        if (kt + 2 < NT) LOAD_TILE(kt + 2, kt & 1);
    }

    // epilogue (optionally tf32-round outputs that feed later GEMMs)
#pragma unroll
    for (int im = 0; im < 4; im++) {
        const int row0 = blockIdx.y * BM + mb + im * 16 + g;
#pragma unroll
        for (int in = 0; in < 4; in++) {
            const int col = blockIdx.x * BN + nb + in * 8 + t * 2;
            float v0 = acc[im][in][0] * alpha, v1 = acc[im][in][1] * alpha;
            float v2 = acc[im][in][2] * alpha, v3 = acc[im][in][3] * alpha;
            if (roundC) { v0 = rtf(v0); v1 = rtf(v1); v2 = rtf(v2); v3 = rtf(v3); }
            if (!transC) {
                *reinterpret_cast<float2*>(&C[(size_t)row0 * ldC + col]) = make_float2(v0, v1);
                *reinterpret_cast<float2*>(&C[(size_t)(row0 + 8) * ldC + col]) = make_float2(v2, v3);
            } else {
                C[(size_t)col * ldC + row0] = v0;
                C[(size_t)(col + 1) * ldC + row0] = v1;
                C[(size_t)col * ldC + row0 + 8] = v2;
                C[(size_t)(col + 1) * ldC + row0 + 8] = v3;
            }
        }
    }
}

// ---------------- row softmax, output rounded to tf32 ----------------------
__global__ void softmax_rows_kernel(float* __restrict__ Sc, int n) {
    float* row = Sc + (size_t)blockIdx.x * n;
    __shared__ float red[256];
    const int t = threadIdx.x;

    float m = -3.4e38f;
    for (int i = t; i < n; i += 256) m = fmaxf(m, row[i]);
    red[t] = m;
    __syncthreads();
    for (int s = 128; s > 0; s >>= 1) {
        if (t < s) red[t] = fmaxf(red[t], red[t + s]);
        __syncthreads();
    }
    m = red[0];
    __syncthreads();

    float sum = 0.f;
    for (int i = t; i < n; i += 256) {
        float e = __expf(row[i] - m);
        row[i] = e;
        sum += e;
    }
    red[t] = sum;
    __syncthreads();
    for (int s = 128; s > 0; s >>= 1) {
        if (t < s) red[t] += red[t + s];
        __syncthreads();
    }
    float inv = 1.0f / red[0];
    __syncthreads();
    for (int i = t; i < n; i += 256) row[i] = rtf(row[i] * inv);
}

// --------------------------------------------------------------------------
extern "C" void kernel_launch(void* const* d_in, const int* in_sizes, int n_in,
                              void* d_out, int out_size) {
    const float* query = (const float*)d_in[0];
    const float* key_  = (const float*)d_in[1];
    const float* value = (const float*)d_in[2];
    const float* Qw = (const float*)d_in[3];
    const float* Kw = (const float*)d_in[4];
    const float* Vw = (const float*)d_in[5];
    const float* QA = (const float*)d_in[6];
    const float* QB = (const float*)d_in[7];
    const float* KA = (const float*)d_in[8];
    const float* KB = (const float*)d_in[9];
    const float* VA = (const float*)d_in[10];
    const float* VB = (const float*)d_in[11];
    const float* Ow = (const float*)d_in[12];
    float* out = (float*)d_out;

    float *weff, *xq, *xk, *xv, *ow, *q, *k, *vT, *scores, *ctx;
    cudaGetSymbolAddress((void**)&weff, g_weff);
    cudaGetSymbolAddress((void**)&xq, g_xq);
    cudaGetSymbolAddress((void**)&xk, g_xk);
    cudaGetSymbolAddress((void**)&xv, g_xv);
    cudaGetSymbolAddress((void**)&ow, g_ow);
    cudaGetSymbolAddress((void**)&q, g_q);
    cudaGetSymbolAddress((void**)&k, g_k);
    cudaGetSymbolAddress((void**)&vT, g_vT);
    cudaGetSymbolAddress((void**)&scores, g_scores);
    cudaGetSymbolAddress((void**)&ctx, g_ctx);
    float* weff_q = weff;
    float* weff_k = weff + (size_t)EDIM * EDIM;
    float* weff_v = weff + (size_t)2 * EDIM * EDIM;

    cudaFuncSetAttribute(gemm_tc_kernel, cudaFuncAttributeMaxDynamicSharedMemorySize, GEMM_SMEM);

    // 0) tf32-round the raw GEMM inputs into scratch
    const size_t nqkv4 = (size_t)MTOT * EDIM / 4;
    round_tf32_kernel<<<nqkv4 / 256, 256>>>((const float4*)query, (float4*)xq);
    round_tf32_kernel<<<nqkv4 / 256, 256>>>((const float4*)key_,  (float4*)xk);
    round_tf32_kernel<<<nqkv4 / 256, 256>>>((const float4*)value, (float4*)xv);
    round_tf32_kernel<<<(size_t)EDIM * EDIM / 4 / 256, 256>>>((const float4*)Ow, (float4*)ow);

    // 1) fold LoRA into effective weights (tf32-rounded at store)
    dim3 gf(EDIM * EDIM / 256, 1, 3);
    fold_lora_kernel<<<gf, 256>>>(Qw, QB, QA, Kw, KB, KA, Vw, VB, VA, weff);

    // 2) projections: [8192,1024] @ Weff^T  (V written transposed; outputs tf32-rounded)
    dim3 gp(EDIM / BN, MTOT / BM, 1);
    gemm_tc_kernel<<<gp, 256, GEMM_SMEM>>>(xq, weff_q, q, EDIM, EDIM, EDIM, EDIM, 1.f, 0, 1, 0, 0, 0);
    gemm_tc_kernel<<<gp, 256, GEMM_SMEM>>>(xk, weff_k, k, EDIM, EDIM, EDIM, EDIM, 1.f, 0, 1, 0, 0, 0);
    gemm_tc_kernel<<<gp, 256, GEMM_SMEM>>>(xv, weff_v, vT, EDIM, EDIM, MTOT, EDIM, 1.f, 1, 1, 0, 0, 0);

    // 3) scores[b] = Q[b] @ K[b]^T / 32  (not rounded; softmax rounds)
    dim3 gs(SLEN / BN, SLEN / BM, BATCH);
    gemm_tc_kernel<<<gs, 256, GEMM_SMEM>>>(q, k, scores, EDIM, EDIM, SLEN, EDIM, 0.03125f, 0, 0,
                                           (long)SLEN * EDIM, (long)SLEN * EDIM, (long)SLEN * SLEN);

    // 4) row softmax (stores tf32-rounded probabilities)
    softmax_rows_kernel<<<BATCH * SLEN, 256>>>(scores, SLEN);

    // 5) ctx[b] = attn[b] @ V[b] (NT via vT; output rounded for next GEMM)
    dim3 gc(EDIM / BN, SLEN / BM, BATCH);
    gemm_tc_kernel<<<gc, 256, GEMM_SMEM>>>(scores, vT, ctx, SLEN, MTOT, EDIM, SLEN, 1.f, 0, 1,
                                           (long)SLEN * SLEN, (long)SLEN, (long)SLEN * EDIM);

    // 6) out = ctx @ O^T (final output, full fp32)
    dim3 go(EDIM / BN, MTOT / BM, 1);
    gemm_tc_kernel<<<go, 256, GEMM_SMEM>>>(ctx, ow, out, EDIM, EDIM, EDIM, EDIM, 1.f, 0, 0, 0, 0, 0);
}

// round 10
// speedup vs baseline: 1.0451x; 1.0451x over previous
#include <cuda_runtime.h>
#include <cstdint>

// Problem dims (fixed by the reference)
#define EDIM 1024
#define RDIM 16
#define BATCH 4
#define SLEN 2048
#define MTOT (BATCH * SLEN)   // 8192

// ---------------- device scratch (no allocations allowed) ----------------
__device__ float g_weff[3][EDIM * EDIM];                 // Q,K,V effective weights (tf32)
__device__ float g_xq[(size_t)MTOT * EDIM];              // tf32 copies of inputs
__device__ float g_xk[(size_t)MTOT * EDIM];
__device__ float g_xv[(size_t)MTOT * EDIM];
__device__ float g_ow[EDIM * EDIM];
__device__ float g_q[(size_t)MTOT * EDIM];
__device__ float g_k[(size_t)MTOT * EDIM];
__device__ float g_vT[(size_t)EDIM * MTOT];              // V projection, transposed
__device__ float g_scores[(size_t)BATCH * SLEN * SLEN];
__device__ float g_ctx[(size_t)MTOT * EDIM];

__device__ __forceinline__ float rtf(float f) {          // round-to-nearest tf32, as fp32 bits
    uint32_t u;
    asm("cvt.rna.tf32.f32 %0, %1;" : "=r"(u) : "f"(f));
    return __uint_as_float(u);
}

// ---- elementwise tf32 rounding copy (float4 granularity) ----
__global__ void round_tf32_kernel(const float4* __restrict__ src, float4* __restrict__ dst) {
    size_t i = (size_t)blockIdx.x * blockDim.x + threadIdx.x;
    float4 v = src[i];
    v.x = rtf(v.x); v.y = rtf(v.y); v.z = rtf(v.z); v.w = rtf(v.w);
    dst[i] = v;
}

// ---- fold LoRA: Weff[f][e] = tf32(W[f][e] + sum_r B[f][r]*A[r][e]) ----
__global__ void fold_lora_kernel(const float* __restrict__ W0, const float* __restrict__ B0,
                                 const float* __restrict__ A0,
                                 const float* __restrict__ W1, const float* __restrict__ B1,
                                 const float* __restrict__ A1,
                                 const float* __restrict__ W2, const float* __restrict__ B2,
                                 const float* __restrict__ A2,
                                 float* __restrict__ Weff) {
    const float *W, *Bm, *Am;
    if (blockIdx.z == 0)      { W = W0; Bm = B0; Am = A0; }
    else if (blockIdx.z == 1) { W = W1; Bm = B1; Am = A1; }
    else                      { W = W2; Bm = B2; Am = A2; }
    float* dst = Weff + (size_t)blockIdx.z * EDIM * EDIM;
    int idx = blockIdx.x * blockDim.x + threadIdx.x;
    int f = idx >> 10;
    int e = idx & (EDIM - 1);
    float acc = W[idx];
#pragma unroll
    for (int r = 0; r < RDIM; r++) acc += Bm[f * RDIM + r] * Am[r * EDIM + e];
    dst[idx] = rtf(acc);
}

// ======== tf32 mma.sync NT GEMM: C[m][n] = alpha * sum_k A[m][k]*B[n][k] ========
// Inputs MUST already be tf32-rounded in memory. Fragments via ldmatrix
// (tf32 elements ride as b16 pairs; tile mapping == mma fragment layout).
// Block tile 128x128x32, 8 warps (2 x 4), warp tile 64x32, mma m16n8k8.
// 3-stage cp.async pipeline; single fragment buffer to stay at <=128 regs
// (2 CTAs/SM: 128 regs x 256 thr x 2 = full 64K RF).
#define BM 128
#define BN 128
#define BK 32
#define NSTAGE 3
#define SMSTRIDE 36                         // floats per row (32 + 4 pad)
#define TILE_F (128 * SMSTRIDE)
#define STAGE_F (2 * TILE_F)
#define STAGE_BYTES (STAGE_F * 4)           // 36864
#define GEMM_SMEM (NSTAGE * STAGE_BYTES)    // 110592 bytes

__device__ __forceinline__ void mma_tf32(float c[4], const uint32_t a[4], const uint32_t b[2]) {
    asm volatile(
        "mma.sync.aligned.m16n8k8.row.col.f32.tf32.tf32.f32 "
        "{%0,%1,%2,%3}, {%4,%5,%6,%7}, {%8,%9}, {%0,%1,%2,%3};"
        : "+f"(c[0]), "+f"(c[1]), "+f"(c[2]), "+f"(c[3])
        : "r"(a[0]), "r"(a[1]), "r"(a[2]), "r"(a[3]), "r"(b[0]), "r"(b[1]));
}

__device__ __forceinline__ void ldsm_x4(uint32_t r[4], uint32_t addr) {
    asm volatile("ldmatrix.sync.aligned.m8n8.x4.shared.b16 {%0,%1,%2,%3}, [%4];"
                 : "=r"(r[0]), "=r"(r[1]), "=r"(r[2]), "=r"(r[3]) : "r"(addr));
}
__device__ __forceinline__ void ldsm_x2(uint32_t r[2], uint32_t addr) {
    asm volatile("ldmatrix.sync.aligned.m8n8.x2.shared.b16 {%0,%1}, [%2];"
                 : "=r"(r[0]), "=r"(r[1]) : "r"(addr));
}

__global__ __launch_bounds__(256, 2) void gemm_tc_kernel(
    const float* __restrict__ A, const float* __restrict__ B, float* __restrict__ C,
    int ldA, int ldB, int ldC, int Kdim, float alpha, int transC, int roundC,
    long sA, long sB, long sC) {
    extern __shared__ __align__(16) float sm[];
    uint32_t smb;
    asm("{ .reg .u64 u; cvta.to.shared.u64 u, %1; cvt.u32.u64 %0, u; }" : "=r"(smb) : "l"(sm));
    A += (size_t)blockIdx.z * sA + (size_t)blockIdx.y * BM * ldA;
    B += (size_t)blockIdx.z * sB + (size_t)blockIdx.x * BN * ldB;
    C += (size_t)blockIdx.z * sC;
    const int tid = threadIdx.x;
    const int wid = tid >> 5, lid = tid & 31;
    const int wm = wid & 1, wn = wid >> 1;      // warp grid 2 x 4
    const int mb = wm * 64, nb = wn * 32;
    const int g = lid >> 2, t = lid & 3;

    // ldmatrix lane->address offsets (bytes, relative to stage base)
    uint32_t a_off[4], b_off[4];
#pragma unroll
    for (int im = 0; im < 4; im++)
        a_off[im] = ((mb + im * 16 + (lid & 15)) * SMSTRIDE + (lid >> 4) * 4) * 4;
#pragma unroll
    for (int in = 0; in < 4; in++)
        b_off[in] = ((nb + in * 8 + (lid & 7)) * SMSTRIDE + ((lid >> 3) & 1) * 4) * 4
                    + TILE_F * 4;

    float acc[4][4][4];
#pragma unroll
    for (int im = 0; im < 4; im++)
#pragma unroll
        for (int in = 0; in < 4; in++)
#pragma unroll
            for (int q = 0; q < 4; q++) acc[im][in][q] = 0.f;

    const int NT = Kdim / BK;

#define LOAD_TILE(KT, S)                                                          \
    do {                                                                          \
        float* as = sm + (S) * STAGE_F;                                           \
        float* bs = as + TILE_F;                                                  \
        const float* Ag = A + (size_t)(KT) * BK;                                  \
        const float* Bg = B + (size_t)(KT) * BK;                                  \
        _Pragma("unroll")                                                         \
        for (int j = 0; j < 4; j++) {                                             \
            int idx = j * 256 + tid;                                              \
            int r = idx >> 3, q = idx & 7;                                        \
            uint32_t so;                                                          \
            asm("{ .reg .u64 u; cvta.to.shared.u64 u, %1; cvt.u32.u64 %0, u; }"   \
                : "=r"(so) : "l"(as + r * SMSTRIDE + q * 4));                     \
            asm volatile("cp.async.cg.shared.global [%0], [%1], 16;"              \
                         :: "r"(so), "l"(Ag + (size_t)r * ldA + q * 4));          \
        }                                                                         \
        _Pragma("unroll")                                                         \
        for (int j = 0; j < 4; j++) {                                             \
            int idx = j * 256 + tid;                                              \
            int r = idx >> 3, q = idx & 7;                                        \
            uint32_t so;                                                          \
            asm("{ .reg .u64 u; cvta.to.shared.u64 u, %1; cvt.u32.u64 %0, u; }"   \
                : "=r"(so) : "l"(bs + r * SMSTRIDE + q * 4));                     \
            asm volatile("cp.async.cg.shared.global [%0], [%1], 16;"              \
                         :: "r"(so), "l"(Bg + (size_t)r * ldB + q * 4));          \
        }                                                                         \
        asm volatile("cp.async.commit_group;" ::: "memory");                      \
    } while (0)

    // prologue: fill first two stages
    LOAD_TILE(0, 0);
    LOAD_TILE(1, 1);

    for (int kt = 0; kt < NT; kt++) {
        if (kt + 1 < NT)
            asm volatile("cp.async.wait_group 1;" ::: "memory");   // tile kt ready
        else
            asm volatile("cp.async.wait_group 0;" ::: "memory");
        __syncthreads();

        // issue next tile load FIRST so DMA overlaps the whole compute phase.
        // stage (kt+2)%NSTAGE was consumed in iteration kt-1; the sync above
        // guarantees every warp is done with it.
        if (kt + 2 < NT) {
            int sp = (kt + 2) % NSTAGE;
            LOAD_TILE(kt + 2, sp);
        }

        const uint32_t stg = smb + (kt % NSTAGE) * STAGE_BYTES;
#pragma unroll
        for (int ks = 0; ks < 4; ks++) {
            const uint32_t ko = ks * 32;    // 8 floats = 32 bytes
            uint32_t ua[4][4], ub[4][2];
#pragma unroll
            for (int im = 0; im < 4; im++) ldsm_x4(ua[im], stg + a_off[im] + ko);
#pragma unroll
            for (int in = 0; in < 4; in++) ldsm_x2(ub[in], stg + b_off[in] + ko);
#pragma unroll
            for (int im = 0; im < 4; im++)
#pragma unroll
                for (int in = 0; in < 4; in++) mma_tf32(acc[im][in], ua[im], ub[in]);
        }
    }

    // epilogue (optionally tf32-round outputs that feed later GEMMs)
#pragma unroll
    for (int im = 0; im < 4; im++) {
        const int row0 = blockIdx.y * BM + mb + im * 16 + g;
#pragma unroll
        for (int in = 0; in < 4; in++) {
            const int col = blockIdx.x * BN + nb + in * 8 + t * 2;
            float v0 = acc[im][in][0] * alpha, v1 = acc[im][in][1] * alpha;
            float v2 = acc[im][in][2] * alpha, v3 = acc[im][in][3] * alpha;
            if (roundC) { v0 = rtf(v0); v1 = rtf(v1); v2 = rtf(v2); v3 = rtf(v3); }
            if (!transC) {
                *reinterpret_cast<float2*>(&C[(size_t)row0 * ldC + col]) = make_float2(v0, v1);
                *reinterpret_cast<float2*>(&C[(size_t)(row0 + 8) * ldC + col]) = make_float2(v2, v3);
            } else {
                C[(size_t)col * ldC + row0] = v0;
                C[(size_t)(col + 1) * ldC + row0] = v1;
                C[(size_t)col * ldC + row0 + 8] = v2;
                C[(size_t)(col + 1) * ldC + row0 + 8] = v3;
            }
        }
    }
}

// ---------------- row softmax, output rounded to tf32 ----------------------
__global__ void softmax_rows_kernel(float* __restrict__ Sc, int n) {
    float* row = Sc + (size_t)blockIdx.x * n;
    __shared__ float red[256];
    const int t = threadIdx.x;

    float m = -3.4e38f;
    for (int i = t; i < n; i += 256) m = fmaxf(m, row[i]);
    red[t] = m;
    __syncthreads();
    for (int s = 128; s > 0; s >>= 1) {
        if (t < s) red[t] = fmaxf(red[t], red[t + s]);
        __syncthreads();
    }
    m = red[0];
    __syncthreads();

    float sum = 0.f;
    for (int i = t; i < n; i += 256) {
        float e = __expf(row[i] - m);
        row[i] = e;
        sum += e;
    }
    red[t] = sum;
    __syncthreads();
    for (int s = 128; s > 0; s >>= 1) {
        if (t < s) red[t] += red[t + s];
        __syncthreads();
    }
    float inv = 1.0f / red[0];
    __syncthreads();
    for (int i = t; i < n; i += 256) row[i] = rtf(row[i] * inv);
}

// --------------------------------------------------------------------------
extern "C" void kernel_launch(void* const* d_in, const int* in_sizes, int n_in,
                              void* d_out, int out_size) {
    const float* query = (const float*)d_in[0];
    const float* key_  = (const float*)d_in[1];
    const float* value = (const float*)d_in[2];
    const float* Qw = (const float*)d_in[3];
    const float* Kw = (const float*)d_in[4];
    const float* Vw = (const float*)d_in[5];
    const float* QA = (const float*)d_in[6];
    const float* QB = (const float*)d_in[7];
    const float* KA = (const float*)d_in[8];
    const float* KB = (const float*)d_in[9];
    const float* VA = (const float*)d_in[10];
    const float* VB = (const float*)d_in[11];
    const float* Ow = (const float*)d_in[12];
    float* out = (float*)d_out;

    float *weff, *xq, *xk, *xv, *ow, *q, *k, *vT, *scores, *ctx;
    cudaGetSymbolAddress((void**)&weff, g_weff);
    cudaGetSymbolAddress((void**)&xq, g_xq);
    cudaGetSymbolAddress((void**)&xk, g_xk);
    cudaGetSymbolAddress((void**)&xv, g_xv);
    cudaGetSymbolAddress((void**)&ow, g_ow);
    cudaGetSymbolAddress((void**)&q, g_q);
    cudaGetSymbolAddress((void**)&k, g_k);
    cudaGetSymbolAddress((void**)&vT, g_vT);
    cudaGetSymbolAddress((void**)&scores, g_scores);
    cudaGetSymbolAddress((void**)&ctx, g_ctx);
    float* weff_q = weff;
    float* weff_k = weff + (size_t)EDIM * EDIM;
    float* weff_v = weff + (size_t)2 * EDIM * EDIM;

    cudaFuncSetAttribute(gemm_tc_kernel, cudaFuncAttributeMaxDynamicSharedMemorySize, GEMM_SMEM);

    // 0) tf32-round the raw GEMM inputs into scratch
    const size_t nqkv4 = (size_t)MTOT * EDIM / 4;
    round_tf32_kernel<<<nqkv4 / 256, 256>>>((const float4*)query, (float4*)xq);
    round_tf32_kernel<<<nqkv4 / 256, 256>>>((const float4*)key_,  (float4*)xk);
    round_tf32_kernel<<<nqkv4 / 256, 256>>>((const float4*)value, (float4*)xv);
    round_tf32_kernel<<<(size_t)EDIM * EDIM / 4 / 256, 256>>>((const float4*)Ow, (float4*)ow);

    // 1) fold LoRA into effective weights (tf32-rounded at store)
    dim3 gf(EDIM * EDIM / 256, 1, 3);
    fold_lora_kernel<<<gf, 256>>>(Qw, QB, QA, Kw, KB, KA, Vw, VB, VA, weff);

    // 2) projections: [8192,1024] @ Weff^T  (V written transposed; outputs tf32-rounded)
    dim3 gp(EDIM / BN, MTOT / BM, 1);
    gemm_tc_kernel<<<gp, 256, GEMM_SMEM>>>(xq, weff_q, q, EDIM, EDIM, EDIM, EDIM, 1.f, 0, 1, 0, 0, 0);
    gemm_tc_kernel<<<gp, 256, GEMM_SMEM>>>(xk, weff_k, k, EDIM, EDIM, EDIM, EDIM, 1.f, 0, 1, 0, 0, 0);
    gemm_tc_kernel<<<gp, 256, GEMM_SMEM>>>(xv, weff_v, vT, EDIM, EDIM, MTOT, EDIM, 1.f, 1, 1, 0, 0, 0);

    // 3) scores[b] = Q[b] @ K[b]^T / 32  (not rounded; softmax rounds)
    dim3 gs(SLEN / BN, SLEN / BM, BATCH);
    gemm_tc_kernel<<<gs, 256, GEMM_SMEM>>>(q, k, scores, EDIM, EDIM, SLEN, EDIM, 0.03125f, 0, 0,
                                           (long)SLEN * EDIM, (long)SLEN * EDIM, (long)SLEN * SLEN);

    // 4) row softmax (stores tf32-rounded probabilities)
    softmax_rows_kernel<<<BATCH * SLEN, 256>>>(scores, SLEN);

    // 5) ctx[b] = attn[b] @ V[b] (NT via vT; output rounded for next GEMM)
    dim3 gc(EDIM / BN, SLEN / BM, BATCH);
    gemm_tc_kernel<<<gc, 256, GEMM_SMEM>>>(scores, vT, ctx, SLEN, MTOT, EDIM, SLEN, 1.f, 0, 1,
                                           (long)SLEN * SLEN, (long)SLEN, (long)SLEN * EDIM);

    // 6) out = ctx @ O^T (final output, full fp32)
    dim3 go(EDIM / BN, MTOT / BM, 1);
    gemm_tc_kernel<<<go, 256, GEMM_SMEM>>>(ctx, ow, out, EDIM, EDIM, EDIM, EDIM, 1.f, 0, 0, 0, 0, 0);
}